// round 2
// baseline (speedup 1.0000x reference)
#include <cuda_runtime.h>
#include <math.h>

// Problem constants
#define Bq   4
#define Tq   2048
#define Cq   1024
#define Hq   16
#define Dq   64
#define NTOK (Bq * Tq)        // 8192
#define C3   (3 * Cq)         // 3072

// Scratch (allocation-free rule: __device__ globals)
__device__ float g_qkv[(size_t)NTOK * C3];   // [B,T,3C] ~100 MB
__device__ float g_y[(size_t)NTOK * Cq];     // [B,T,C]  ~33 MB

// ---------------------------------------------------------------------------
// SGEMM: C[M,N] = A[M,K] * Bw[N,K]^T + bias[N]
// 128x128 tile, BK=16, 256 threads, 8x8 micro-tile, register prefetch.
// M,N,K all multiples of tile sizes for this problem.
// ---------------------------------------------------------------------------
__global__ __launch_bounds__(256, 2)
void sgemm_bias_kernel(const float* __restrict__ A,
                       const float* __restrict__ Bw,
                       const float* __restrict__ bias,
                       float* __restrict__ C,
                       int M, int N, int K)
{
    __shared__ float As[16][132];
    __shared__ float Bs[16][132];

    const int tid = threadIdx.x;
    const int tx  = tid & 15;
    const int ty  = tid >> 4;
    const int m0  = blockIdx.y * 128;
    const int n0  = blockIdx.x * 128;

    // loader mapping: each thread loads one 8-float half-row per tile
    const int lr = tid >> 1;          // 0..127
    const int lc = (tid & 1) * 8;     // 0 or 8

    const float* Aptr = A  + (size_t)(m0 + lr) * K + lc;
    const float* Bptr = Bw + (size_t)(n0 + lr) * K + lc;

    float4 a0 = *(const float4*)(Aptr);
    float4 a1 = *(const float4*)(Aptr + 4);
    float4 b0 = *(const float4*)(Bptr);
    float4 b1 = *(const float4*)(Bptr + 4);

    float acc[8][8];
#pragma unroll
    for (int i = 0; i < 8; i++)
#pragma unroll
        for (int j = 0; j < 8; j++) acc[i][j] = 0.f;

    for (int k0 = 0; k0 < K; k0 += 16) {
        // store prefetched tile (transposed: [k][row])
        As[lc + 0][lr] = a0.x; As[lc + 1][lr] = a0.y;
        As[lc + 2][lr] = a0.z; As[lc + 3][lr] = a0.w;
        As[lc + 4][lr] = a1.x; As[lc + 5][lr] = a1.y;
        As[lc + 6][lr] = a1.z; As[lc + 7][lr] = a1.w;
        Bs[lc + 0][lr] = b0.x; Bs[lc + 1][lr] = b0.y;
        Bs[lc + 2][lr] = b0.z; Bs[lc + 3][lr] = b0.w;
        Bs[lc + 4][lr] = b1.x; Bs[lc + 5][lr] = b1.y;
        Bs[lc + 6][lr] = b1.z; Bs[lc + 7][lr] = b1.w;
        __syncthreads();

        if (k0 + 16 < K) {
            a0 = *(const float4*)(Aptr + k0 + 16);
            a1 = *(const float4*)(Aptr + k0 + 20);
            b0 = *(const float4*)(Bptr + k0 + 16);
            b1 = *(const float4*)(Bptr + k0 + 20);
        }

#pragma unroll
        for (int kk = 0; kk < 16; kk++) {
            float ar[8], br[8];
            *(float4*)&ar[0] = *(const float4*)&As[kk][ty * 8];
            *(float4*)&ar[4] = *(const float4*)&As[kk][ty * 8 + 4];
            *(float4*)&br[0] = *(const float4*)&Bs[kk][tx * 8];
            *(float4*)&br[4] = *(const float4*)&Bs[kk][tx * 8 + 4];
#pragma unroll
            for (int i = 0; i < 8; i++)
#pragma unroll
                for (int j = 0; j < 8; j++)
                    acc[i][j] = fmaf(ar[i], br[j], acc[i][j]);
        }
        __syncthreads();
    }

    float bres[8];
#pragma unroll
    for (int j = 0; j < 8; j++) bres[j] = bias[n0 + tx * 8 + j];

#pragma unroll
    for (int i = 0; i < 8; i++) {
        const int m = m0 + ty * 8 + i;
        float4 o0, o1;
        o0.x = acc[i][0] + bres[0]; o0.y = acc[i][1] + bres[1];
        o0.z = acc[i][2] + bres[2]; o0.w = acc[i][3] + bres[3];
        o1.x = acc[i][4] + bres[4]; o1.y = acc[i][5] + bres[5];
        o1.z = acc[i][6] + bres[6]; o1.w = acc[i][7] + bres[7];
        *(float4*)(C + (size_t)m * N + n0 + tx * 8)     = o0;
        *(float4*)(C + (size_t)m * N + n0 + tx * 8 + 4) = o1;
    }
}

// ---------------------------------------------------------------------------
// Flash attention (causal), fp32. One block per (b, h, q-tile of 64).
// 256 threads, 4x4 micro-tiles, online softmax with 16-lane shuffle reductions.
// qkv layout: [B,T,3C]; q at col h*64, k at 1024+h*64, v at 2048+h*64.
// ---------------------------------------------------------------------------
#define FS 68   // padded smem row stride (floats); 68*4 bytes = 16B-aligned rows

__global__ __launch_bounds__(256, 2)
void flash_attn_kernel(const float* __restrict__ qkv, float* __restrict__ y)
{
    extern __shared__ float sm[];
    float* Qs = sm;                 // [64][FS] transposed: Qs[d*FS + r]
    float* Ks = Qs + 64 * FS;       // [64][FS] transposed: Ks[d*FS + j]
    float* Vs = Ks + 64 * FS;       // [64][FS] natural:    Vs[j*FS + d]
    float* Ps = Vs + 64 * FS;       // [64][FS] natural:    Ps[r*FS + j]

    const int tid = threadIdx.x;
    const int tx  = tid & 15;       // k-cols (S phase) / d-cols (O phase): tx*4..+3
    const int ty  = tid >> 4;       // q-rows: ty*4..+3
    const int qt  = blockIdx.x;
    const int bh  = blockIdx.y;
    const int b   = bh >> 4;
    const int h   = bh & 15;
    const int q0  = qt * 64;

    const float* base = qkv + (size_t)b * Tq * C3 + h * Dq;

    // loader mapping: 4 threads per row, 16 floats each
    const int lr = tid >> 2;            // 0..63
    const int ld = (tid & 3) * 16;      // 0,16,32,48

    // load Q (pre-scaled by 1/sqrt(D)=0.125), transposed
    {
        const float* qp = base + (size_t)(q0 + lr) * C3 + ld;
#pragma unroll
        for (int u = 0; u < 4; ++u) {
            float4 v = *(const float4*)(qp + u * 4);
            int d = ld + u * 4;
            Qs[(d + 0) * FS + lr] = v.x * 0.125f;
            Qs[(d + 1) * FS + lr] = v.y * 0.125f;
            Qs[(d + 2) * FS + lr] = v.z * 0.125f;
            Qs[(d + 3) * FS + lr] = v.w * 0.125f;
        }
    }

    float o[4][4];
#pragma unroll
    for (int i = 0; i < 4; i++)
#pragma unroll
        for (int j = 0; j < 4; j++) o[i][j] = 0.f;
    float mrow[4] = {-1e30f, -1e30f, -1e30f, -1e30f};
    float lsum[4] = {0.f, 0.f, 0.f, 0.f};

    for (int jt = 0; jt <= qt; ++jt) {
        const int k0 = jt * 64;
        __syncthreads();   // protect Vs/Ps of previous iter (and Qs on first)

        // load K (transposed) and V (natural)
        {
            const float* kp = base + Cq     + (size_t)(k0 + lr) * C3 + ld;
            const float* vp = base + 2 * Cq + (size_t)(k0 + lr) * C3 + ld;
#pragma unroll
            for (int u = 0; u < 4; ++u) {
                float4 kv = *(const float4*)(kp + u * 4);
                int d = ld + u * 4;
                Ks[(d + 0) * FS + lr] = kv.x;
                Ks[(d + 1) * FS + lr] = kv.y;
                Ks[(d + 2) * FS + lr] = kv.z;
                Ks[(d + 3) * FS + lr] = kv.w;
                float4 vv = *(const float4*)(vp + u * 4);
                *(float4*)&Vs[lr * FS + d] = vv;
            }
        }
        __syncthreads();

        // S = (Q*scale) @ K^T   (4x4 per thread)
        float s[4][4];
#pragma unroll
        for (int i = 0; i < 4; i++)
#pragma unroll
            for (int j = 0; j < 4; j++) s[i][j] = 0.f;

#pragma unroll 8
        for (int kk = 0; kk < 64; ++kk) {
            float4 a  = *(const float4*)&Qs[kk * FS + ty * 4];
            float4 bk = *(const float4*)&Ks[kk * FS + tx * 4];
            float ar[4] = {a.x, a.y, a.z, a.w};
            float br[4] = {bk.x, bk.y, bk.z, bk.w};
#pragma unroll
            for (int i = 0; i < 4; i++)
#pragma unroll
                for (int j = 0; j < 4; j++)
                    s[i][j] = fmaf(ar[i], br[j], s[i][j]);
        }

        if (jt == qt) {  // causal mask on diagonal tile (q0 == k0)
#pragma unroll
            for (int i = 0; i < 4; i++)
#pragma unroll
                for (int j = 0; j < 4; j++)
                    if (tx * 4 + j > ty * 4 + i) s[i][j] = -1e30f;
        }

        // online softmax update (per q-row, reduce across 16 tx lanes)
#pragma unroll
        for (int i = 0; i < 4; i++) {
            float mx = fmaxf(fmaxf(s[i][0], s[i][1]), fmaxf(s[i][2], s[i][3]));
#pragma unroll
            for (int off = 1; off < 16; off <<= 1)
                mx = fmaxf(mx, __shfl_xor_sync(0xffffffffu, mx, off, 16));
            const float mnew  = fmaxf(mrow[i], mx);
            const float alpha = __expf(mrow[i] - mnew);
            mrow[i] = mnew;
            float rs = 0.f;
#pragma unroll
            for (int j = 0; j < 4; j++) {
                float p = __expf(s[i][j] - mnew);
                s[i][j] = p;
                rs += p;
            }
#pragma unroll
            for (int off = 1; off < 16; off <<= 1)
                rs += __shfl_xor_sync(0xffffffffu, rs, off, 16);
            lsum[i] = lsum[i] * alpha + rs;
#pragma unroll
            for (int j = 0; j < 4; j++) o[i][j] *= alpha;
        }

        // write P (natural layout, float4 per row)
#pragma unroll
        for (int i = 0; i < 4; i++) {
            float4 p4 = make_float4(s[i][0], s[i][1], s[i][2], s[i][3]);
            *(float4*)&Ps[(ty * 4 + i) * FS + tx * 4] = p4;
        }
        __syncthreads();

        // O += P @ V
#pragma unroll 8
        for (int jj = 0; jj < 64; ++jj) {
            float p0 = Ps[(ty * 4 + 0) * FS + jj];
            float p1 = Ps[(ty * 4 + 1) * FS + jj];
            float p2 = Ps[(ty * 4 + 2) * FS + jj];
            float p3 = Ps[(ty * 4 + 3) * FS + jj];
            float4 v4 = *(const float4*)&Vs[jj * FS + tx * 4];
            float vr[4] = {v4.x, v4.y, v4.z, v4.w};
#pragma unroll
            for (int j = 0; j < 4; j++) {
                o[0][j] = fmaf(p0, vr[j], o[0][j]);
                o[1][j] = fmaf(p1, vr[j], o[1][j]);
                o[2][j] = fmaf(p2, vr[j], o[2][j]);
                o[3][j] = fmaf(p3, vr[j], o[3][j]);
            }
        }
    }

    // epilogue: normalize, write y[B,T,C] (head h cols)
#pragma unroll
    for (int i = 0; i < 4; i++) {
        const float inv = 1.f / lsum[i];
        float4 o4 = make_float4(o[i][0] * inv, o[i][1] * inv,
                                o[i][2] * inv, o[i][3] * inv);
        const size_t row = (size_t)(b * Tq + q0 + ty * 4 + i);
        *(float4*)(y + row * Cq + h * Dq + tx * 4) = o4;
    }
}

#define FLASH_SMEM (4 * 64 * FS * sizeof(float))   // 69632 bytes

// ---------------------------------------------------------------------------
extern "C" void kernel_launch(void* const* d_in, const int* in_sizes, int n_in,
                              void* d_out, int out_size)
{
    const float* x      = (const float*)d_in[0];
    const float* w_attn = (const float*)d_in[1];
    const float* b_attn = (const float*)d_in[2];
    const float* w_proj = (const float*)d_in[3];
    const float* b_proj = (const float*)d_in[4];
    float* out = (float*)d_out;

    float *qkv, *yb;
    cudaGetSymbolAddress((void**)&qkv, g_qkv);
    cudaGetSymbolAddress((void**)&yb,  g_y);

    cudaFuncSetAttribute(flash_attn_kernel,
                         cudaFuncAttributeMaxDynamicSharedMemorySize,
                         (int)FLASH_SMEM);

    // 1) qkv = x @ w_attn^T + b_attn
    {
        dim3 grid(C3 / 128, NTOK / 128);
        sgemm_bias_kernel<<<grid, 256>>>(x, w_attn, b_attn, qkv, NTOK, C3, Cq);
    }
    // 2) flash attention -> y
    {
        dim3 grid(Tq / 64, Bq * Hq);
        flash_attn_kernel<<<grid, 256, FLASH_SMEM>>>(qkv, yb);
    }
    // 3) out = y @ w_proj^T + b_proj
    {
        dim3 grid(Cq / 128, NTOK / 128);
        sgemm_bias_kernel<<<grid, 256>>>(yb, w_proj, b_proj, out, NTOK, Cq, Cq);
    }
}

// round 4
// speedup vs baseline: 1.4233x; 1.4233x over previous
#include <cuda_runtime.h>
#include <cuda_bf16.h>
#include <math.h>
#include <stdint.h>

// Problem constants
#define Bq   4
#define Tq   2048
#define Cq   1024
#define Hq   16
#define Dq   64
#define NTOK (Bq * Tq)        // 8192
#define C3   (3 * Cq)         // 3072

// ---------------------------------------------------------------------------
// Scratch (allocation-free rule: __device__ globals)
// ---------------------------------------------------------------------------
__device__ float g_qkv[(size_t)NTOK * C3];   // [B,T,3C] fp32
__device__ float g_y[(size_t)NTOK * Cq];     // [B,T,C]  fp32
__device__ __nv_bfloat16 g_xh[(size_t)NTOK * Cq];
__device__ __nv_bfloat16 g_xl[(size_t)NTOK * Cq];
__device__ __nv_bfloat16 g_wah[(size_t)C3 * Cq];
__device__ __nv_bfloat16 g_wal[(size_t)C3 * Cq];
__device__ __nv_bfloat16 g_yh[(size_t)NTOK * Cq];
__device__ __nv_bfloat16 g_yl[(size_t)NTOK * Cq];
__device__ __nv_bfloat16 g_wph[(size_t)Cq * Cq];
__device__ __nv_bfloat16 g_wpl[(size_t)Cq * Cq];

// ---------------------------------------------------------------------------
// Portable PTX helpers (sm_80+ only: cp.async, ldmatrix, mma.sync)
// ---------------------------------------------------------------------------
__device__ __forceinline__ uint32_t s2u(const void* p) {
    uint32_t a;
    asm("{ .reg .u64 t; cvta.to.shared.u64 t, %1; cvt.u32.u64 %0, t; }"
        : "=r"(a) : "l"(p));
    return a;
}
__device__ __forceinline__ void cp16(uint32_t s, const void* g) {
    asm volatile("cp.async.cg.shared.global [%0], [%1], 16;"
                 :: "r"(s), "l"(g) : "memory");
}
#define CP_COMMIT() asm volatile("cp.async.commit_group;" ::: "memory")
#define CP_WAIT1()  asm volatile("cp.async.wait_group 1;" ::: "memory")

__device__ __forceinline__ void ldsm4(uint32_t& r0, uint32_t& r1,
                                      uint32_t& r2, uint32_t& r3, uint32_t a) {
    asm volatile("ldmatrix.sync.aligned.m8n8.x4.shared.b16 {%0,%1,%2,%3}, [%4];"
                 : "=r"(r0), "=r"(r1), "=r"(r2), "=r"(r3) : "r"(a));
}
__device__ __forceinline__ void mma16816(float* c, const uint32_t* a,
                                         const uint32_t* b) {
    asm volatile("mma.sync.aligned.m16n8k16.row.col.f32.bf16.bf16.f32 "
                 "{%0,%1,%2,%3}, {%4,%5,%6,%7}, {%8,%9}, {%0,%1,%2,%3};"
                 : "+f"(c[0]), "+f"(c[1]), "+f"(c[2]), "+f"(c[3])
                 : "r"(a[0]), "r"(a[1]), "r"(a[2]), "r"(a[3]),
                   "r"(b[0]), "r"(b[1]));
}

// ---------------------------------------------------------------------------
// fp32 -> (bf16 hi, bf16 lo) split
// ---------------------------------------------------------------------------
__global__ void split_kernel(const float* __restrict__ src,
                             __nv_bfloat16* __restrict__ hi,
                             __nv_bfloat16* __restrict__ lo, int n)
{
    int i = (blockIdx.x * blockDim.x + threadIdx.x) * 4;
    if (i >= n) return;
    float4 v = *(const float4*)(src + i);
    float vv[4] = {v.x, v.y, v.z, v.w};
    __nv_bfloat162 h2[2], l2[2];
#pragma unroll
    for (int j = 0; j < 2; j++) {
        __nv_bfloat16 h0 = __float2bfloat16(vv[2*j]);
        __nv_bfloat16 h1 = __float2bfloat16(vv[2*j+1]);
        __nv_bfloat16 l0 = __float2bfloat16(vv[2*j]   - __bfloat162float(h0));
        __nv_bfloat16 l1 = __float2bfloat16(vv[2*j+1] - __bfloat162float(h1));
        h2[j] = __nv_bfloat162(h0, h1);
        l2[j] = __nv_bfloat162(l0, l1);
    }
    *(uint2*)(hi + i) = *(uint2*)h2;
    *(uint2*)(lo + i) = *(uint2*)l2;
}

// ---------------------------------------------------------------------------
// HMMA GEMM: C[M,N] = (Ah+Al)[M,K] @ ((Bh+Bl)[N,K])^T + bias[N]
// split-bf16: D += Ah*Bh + Ah*Bl + Al*Bh  (fp32 accumulate in registers)
//
// 128x128x32 block tile, 3-stage cp.async pipe, 8 warps (4m x 2n),
// warp tile 32x64, mma.sync m16n8k16 + ldmatrix.x4 with XOR swizzle.
// Smem tile rows are 64B (32 bf16); chunk c (16B unit) stored at c^(row&3).
// ---------------------------------------------------------------------------
#define BM 128
#define BN 128
#define BK 32
#define STAGES 3
#define MAT_B   (BM * 64)            // 8192 bytes per matrix tile
#define STAGE_B (4 * MAT_B)          // 32768 (Ah, Al, Bh, Bl)
#define GEMM_SMEM (STAGES * STAGE_B) // 98304

__global__ __launch_bounds__(256, 1)
void gemm_hmma(const __nv_bfloat16* __restrict__ Ah, const __nv_bfloat16* __restrict__ Al,
               const __nv_bfloat16* __restrict__ Bh, const __nv_bfloat16* __restrict__ Bl,
               const float* __restrict__ bias, float* __restrict__ C,
               int M, int N, int K)
{
    extern __shared__ __align__(1024) char smem[];
    const uint32_t sbase = s2u(smem);
    const int tid  = threadIdx.x;
    const int wid  = tid >> 5;
    const int lane = tid & 31;
    const int m0 = blockIdx.y * BM;
    const int n0 = blockIdx.x * BN;
    const int NC = K / BK;           // 32

    const int wm = (wid >> 1) * 32;  // warp m offset (4 warps)
    const int wn = (wid & 1) * 64;   // warp n offset (2 warps)

    // loader mapping: per matrix, thread covers row=tid>>1, chunks (tid&1)*2, +1
    const int lrow = tid >> 1;
    const int lcs  = (tid & 1) * 2;
    const uint32_t so0 = lrow * 64 + ((lcs ^ (lrow & 3)) << 4);
    const uint32_t so1 = lrow * 64 + (((lcs + 1) ^ (lrow & 3)) << 4);

    const __nv_bfloat16* gAh = Ah + (size_t)(m0 + lrow) * K + lcs * 8;
    const __nv_bfloat16* gAl = Al + (size_t)(m0 + lrow) * K + lcs * 8;
    const __nv_bfloat16* gBh = Bh + (size_t)(n0 + lrow) * K + lcs * 8;
    const __nv_bfloat16* gBl = Bl + (size_t)(n0 + lrow) * K + lcs * 8;

    auto load_stage = [&](int st, int c) {
        const uint32_t sb = sbase + st * STAGE_B;
        const int off = c * BK;
        cp16(sb + so0,              gAh + off);
        cp16(sb + so1,              gAh + off + 8);
        cp16(sb + MAT_B   + so0,    gAl + off);
        cp16(sb + MAT_B   + so1,    gAl + off + 8);
        cp16(sb + 2*MAT_B + so0,    gBh + off);
        cp16(sb + 2*MAT_B + so1,    gBh + off + 8);
        cp16(sb + 3*MAT_B + so0,    gBl + off);
        cp16(sb + 3*MAT_B + so1,    gBl + off + 8);
    };

    float acc[2][8][4];
#pragma unroll
    for (int i = 0; i < 2; i++)
#pragma unroll
        for (int j = 0; j < 8; j++)
#pragma unroll
            for (int k = 0; k < 4; k++) acc[i][j][k] = 0.f;

    // ldmatrix per-lane row/chunk bases
    const int g   = lane >> 3;
    const int l7  = lane & 7;
    const int arow = wm + (g & 1) * 8 + l7;        // + mt*16
    const int achk = g >> 1;                       // + 2s
    const int brow = wn + ((g & 2) << 2) + l7;     // + ng*16
    const int bchk = g & 1;                        // + 2s

    // prologue
    load_stage(0, 0); CP_COMMIT();
    load_stage(1, 1); CP_COMMIT();

    for (int c = 0; c < NC; c++) {
        const int st = c % STAGES;
        CP_WAIT1();
        __syncthreads();

        if (c + 2 < NC) load_stage((c + 2) % STAGES, c + 2);
        CP_COMMIT();

        const uint32_t sb  = sbase + st * STAGE_B;
        const uint32_t sAh = sb;
        const uint32_t sAl = sb + MAT_B;
        const uint32_t sBh = sb + 2 * MAT_B;
        const uint32_t sBl = sb + 3 * MAT_B;

#pragma unroll
        for (int s = 0; s < 2; s++) {
            uint32_t ah[2][4], al[2][4];
#pragma unroll
            for (int mt = 0; mt < 2; mt++) {
                const int r = arow + mt * 16;
                const int ck = achk + 2 * s;
                const uint32_t ad = r * 64 + ((ck ^ (r & 3)) << 4);
                ldsm4(ah[mt][0], ah[mt][1], ah[mt][2], ah[mt][3], sAh + ad);
                ldsm4(al[mt][0], al[mt][1], al[mt][2], al[mt][3], sAl + ad);
            }
#pragma unroll
            for (int ng = 0; ng < 4; ng++) {
                const int r = brow + ng * 16;
                const int ck = bchk + 2 * s;
                const uint32_t bd = r * 64 + ((ck ^ (r & 3)) << 4);
                uint32_t bh[4], bl[4];
                ldsm4(bh[0], bh[1], bh[2], bh[3], sBh + bd);
                ldsm4(bl[0], bl[1], bl[2], bl[3], sBl + bd);
#pragma unroll
                for (int mt = 0; mt < 2; mt++) {
                    mma16816(acc[mt][2*ng],   ah[mt], bh);
                    mma16816(acc[mt][2*ng+1], ah[mt], bh + 2);
                    mma16816(acc[mt][2*ng],   ah[mt], bl);
                    mma16816(acc[mt][2*ng+1], ah[mt], bl + 2);
                    mma16816(acc[mt][2*ng],   al[mt], bh);
                    mma16816(acc[mt][2*ng+1], al[mt], bh + 2);
                }
            }
        }
        __syncthreads();
    }

    // epilogue: acc -> C (+bias)
    const int r = lane >> 2;
    const int t = lane & 3;
#pragma unroll
    for (int nt = 0; nt < 8; nt++) {
        const int col = n0 + wn + nt * 8 + t * 2;
        const float2 bv = *(const float2*)(bias + col);
#pragma unroll
        for (int mt = 0; mt < 2; mt++) {
            const int row0 = m0 + wm + mt * 16 + r;
            float2 o0, o1;
            o0.x = acc[mt][nt][0] + bv.x;  o0.y = acc[mt][nt][1] + bv.y;
            o1.x = acc[mt][nt][2] + bv.x;  o1.y = acc[mt][nt][3] + bv.y;
            *(float2*)(C + (size_t)row0 * N + col)       = o0;
            *(float2*)(C + (size_t)(row0 + 8) * N + col) = o1;
        }
    }
}

// ---------------------------------------------------------------------------
// Flash attention (causal), fp32 — unchanged from the passing round-0 kernel.
// ---------------------------------------------------------------------------
#define FS 68

__global__ __launch_bounds__(256, 2)
void flash_attn_kernel(const float* __restrict__ qkv, float* __restrict__ y)
{
    extern __shared__ float sm[];
    float* Qs = sm;
    float* Ks = Qs + 64 * FS;
    float* Vs = Ks + 64 * FS;
    float* Ps = Vs + 64 * FS;

    const int tid = threadIdx.x;
    const int tx  = tid & 15;
    const int ty  = tid >> 4;
    const int qt  = blockIdx.x;
    const int bh  = blockIdx.y;
    const int b   = bh >> 4;
    const int h   = bh & 15;
    const int q0  = qt * 64;

    const float* base = qkv + (size_t)b * Tq * C3 + h * Dq;

    const int lr = tid >> 2;
    const int ld = (tid & 3) * 16;

    {
        const float* qp = base + (size_t)(q0 + lr) * C3 + ld;
#pragma unroll
        for (int u = 0; u < 4; ++u) {
            float4 v = *(const float4*)(qp + u * 4);
            int d = ld + u * 4;
            Qs[(d + 0) * FS + lr] = v.x * 0.125f;
            Qs[(d + 1) * FS + lr] = v.y * 0.125f;
            Qs[(d + 2) * FS + lr] = v.z * 0.125f;
            Qs[(d + 3) * FS + lr] = v.w * 0.125f;
        }
    }

    float o[4][4];
#pragma unroll
    for (int i = 0; i < 4; i++)
#pragma unroll
        for (int j = 0; j < 4; j++) o[i][j] = 0.f;
    float mrow[4] = {-1e30f, -1e30f, -1e30f, -1e30f};
    float lsum[4] = {0.f, 0.f, 0.f, 0.f};

    for (int jt = 0; jt <= qt; ++jt) {
        const int k0 = jt * 64;
        __syncthreads();

        {
            const float* kp = base + Cq     + (size_t)(k0 + lr) * C3 + ld;
            const float* vp = base + 2 * Cq + (size_t)(k0 + lr) * C3 + ld;
#pragma unroll
            for (int u = 0; u < 4; ++u) {
                float4 kv = *(const float4*)(kp + u * 4);
                int d = ld + u * 4;
                Ks[(d + 0) * FS + lr] = kv.x;
                Ks[(d + 1) * FS + lr] = kv.y;
                Ks[(d + 2) * FS + lr] = kv.z;
                Ks[(d + 3) * FS + lr] = kv.w;
                float4 vv = *(const float4*)(vp + u * 4);
                *(float4*)&Vs[lr * FS + d] = vv;
            }
        }
        __syncthreads();

        float s[4][4];
#pragma unroll
        for (int i = 0; i < 4; i++)
#pragma unroll
            for (int j = 0; j < 4; j++) s[i][j] = 0.f;

#pragma unroll 8
        for (int kk = 0; kk < 64; ++kk) {
            float4 a  = *(const float4*)&Qs[kk * FS + ty * 4];
            float4 bk = *(const float4*)&Ks[kk * FS + tx * 4];
            float ar[4] = {a.x, a.y, a.z, a.w};
            float br[4] = {bk.x, bk.y, bk.z, bk.w};
#pragma unroll
            for (int i = 0; i < 4; i++)
#pragma unroll
                for (int j = 0; j < 4; j++)
                    s[i][j] = fmaf(ar[i], br[j], s[i][j]);
        }

        if (jt == qt) {
#pragma unroll
            for (int i = 0; i < 4; i++)
#pragma unroll
                for (int j = 0; j < 4; j++)
                    if (tx * 4 + j > ty * 4 + i) s[i][j] = -1e30f;
        }

#pragma unroll
        for (int i = 0; i < 4; i++) {
            float mx = fmaxf(fmaxf(s[i][0], s[i][1]), fmaxf(s[i][2], s[i][3]));
#pragma unroll
            for (int off = 1; off < 16; off <<= 1)
                mx = fmaxf(mx, __shfl_xor_sync(0xffffffffu, mx, off, 16));
            const float mnew  = fmaxf(mrow[i], mx);
            const float alpha = __expf(mrow[i] - mnew);
            mrow[i] = mnew;
            float rs = 0.f;
#pragma unroll
            for (int j = 0; j < 4; j++) {
                float p = __expf(s[i][j] - mnew);
                s[i][j] = p;
                rs += p;
            }
#pragma unroll
            for (int off = 1; off < 16; off <<= 1)
                rs += __shfl_xor_sync(0xffffffffu, rs, off, 16);
            lsum[i] = lsum[i] * alpha + rs;
#pragma unroll
            for (int j = 0; j < 4; j++) o[i][j] *= alpha;
        }

#pragma unroll
        for (int i = 0; i < 4; i++) {
            float4 p4 = make_float4(s[i][0], s[i][1], s[i][2], s[i][3]);
            *(float4*)&Ps[(ty * 4 + i) * FS + tx * 4] = p4;
        }
        __syncthreads();

#pragma unroll 8
        for (int jj = 0; jj < 64; ++jj) {
            float p0 = Ps[(ty * 4 + 0) * FS + jj];
            float p1 = Ps[(ty * 4 + 1) * FS + jj];
            float p2 = Ps[(ty * 4 + 2) * FS + jj];
            float p3 = Ps[(ty * 4 + 3) * FS + jj];
            float4 v4 = *(const float4*)&Vs[jj * FS + tx * 4];
            float vr[4] = {v4.x, v4.y, v4.z, v4.w};
#pragma unroll
            for (int j = 0; j < 4; j++) {
                o[0][j] = fmaf(p0, vr[j], o[0][j]);
                o[1][j] = fmaf(p1, vr[j], o[1][j]);
                o[2][j] = fmaf(p2, vr[j], o[2][j]);
                o[3][j] = fmaf(p3, vr[j], o[3][j]);
            }
        }
    }

#pragma unroll
    for (int i = 0; i < 4; i++) {
        const float inv = 1.f / lsum[i];
        float4 o4 = make_float4(o[i][0] * inv, o[i][1] * inv,
                                o[i][2] * inv, o[i][3] * inv);
        const size_t row = (size_t)(b * Tq + q0 + ty * 4 + i);
        *(float4*)(y + row * Cq + h * Dq + tx * 4) = o4;
    }
}

#define FLASH_SMEM (4 * 64 * FS * sizeof(float))

// ---------------------------------------------------------------------------
extern "C" void kernel_launch(void* const* d_in, const int* in_sizes, int n_in,
                              void* d_out, int out_size)
{
    const float* x      = (const float*)d_in[0];
    const float* w_attn = (const float*)d_in[1];
    const float* b_attn = (const float*)d_in[2];
    const float* w_proj = (const float*)d_in[3];
    const float* b_proj = (const float*)d_in[4];
    float* out = (float*)d_out;

    float *qkv, *yb;
    __nv_bfloat16 *xh, *xl, *wah, *wal, *yh, *yl, *wph, *wpl;
    cudaGetSymbolAddress((void**)&qkv, g_qkv);
    cudaGetSymbolAddress((void**)&yb,  g_y);
    cudaGetSymbolAddress((void**)&xh,  g_xh);
    cudaGetSymbolAddress((void**)&xl,  g_xl);
    cudaGetSymbolAddress((void**)&wah, g_wah);
    cudaGetSymbolAddress((void**)&wal, g_wal);
    cudaGetSymbolAddress((void**)&yh,  g_yh);
    cudaGetSymbolAddress((void**)&yl,  g_yl);
    cudaGetSymbolAddress((void**)&wph, g_wph);
    cudaGetSymbolAddress((void**)&wpl, g_wpl);

    cudaFuncSetAttribute(flash_attn_kernel,
                         cudaFuncAttributeMaxDynamicSharedMemorySize,
                         (int)FLASH_SMEM);
    cudaFuncSetAttribute(gemm_hmma,
                         cudaFuncAttributeMaxDynamicSharedMemorySize,
                         GEMM_SMEM);

    // splits (fp32 -> bf16 hi/lo)
    {
        int n1 = NTOK * Cq;
        split_kernel<<<(n1 / 4 + 255) / 256, 256>>>(x, xh, xl, n1);
        int n2 = C3 * Cq;
        split_kernel<<<(n2 / 4 + 255) / 256, 256>>>(w_attn, wah, wal, n2);
        int n3 = Cq * Cq;
        split_kernel<<<(n3 / 4 + 255) / 256, 256>>>(w_proj, wph, wpl, n3);
    }

    // 1) qkv = x @ w_attn^T + b_attn   (HMMA, split bf16)
    {
        dim3 grid(C3 / BN, NTOK / BM);
        gemm_hmma<<<grid, 256, GEMM_SMEM>>>(xh, xl, wah, wal, b_attn, qkv,
                                            NTOK, C3, Cq);
    }
    // 2) flash attention -> y (fp32)
    {
        dim3 grid(Tq / 64, Bq * Hq);
        flash_attn_kernel<<<grid, 256, FLASH_SMEM>>>(qkv, yb);
    }
    // split y
    {
        int n = NTOK * Cq;
        split_kernel<<<(n / 4 + 255) / 256, 256>>>(yb, yh, yl, n);
    }
    // 3) out = y @ w_proj^T + b_proj   (HMMA, split bf16)
    {
        dim3 grid(Cq / BN, NTOK / BM);
        gemm_hmma<<<grid, 256, GEMM_SMEM>>>(yh, yl, wph, wpl, b_proj, out,
                                            NTOK, Cq, Cq);
    }
}

// round 5
// speedup vs baseline: 1.6244x; 1.1413x over previous
#include <cuda_runtime.h>
#include <cuda_bf16.h>
#include <math.h>
#include <stdint.h>

// Problem constants
#define Bq   4
#define Tq   2048
#define Cq   1024
#define Hq   16
#define Dq   64
#define NTOK (Bq * Tq)        // 8192
#define C3   (3 * Cq)         // 3072

// ---------------------------------------------------------------------------
// Scratch (allocation-free rule: __device__ globals)
// ---------------------------------------------------------------------------
__device__ __nv_bfloat16 g_qkvh[(size_t)NTOK * C3];
__device__ __nv_bfloat16 g_qkvl[(size_t)NTOK * C3];
__device__ __nv_bfloat16 g_xh[(size_t)NTOK * Cq];
__device__ __nv_bfloat16 g_xl[(size_t)NTOK * Cq];
__device__ __nv_bfloat16 g_wah[(size_t)C3 * Cq];
__device__ __nv_bfloat16 g_wal[(size_t)C3 * Cq];
__device__ __nv_bfloat16 g_yh[(size_t)NTOK * Cq];
__device__ __nv_bfloat16 g_yl[(size_t)NTOK * Cq];
__device__ __nv_bfloat16 g_wph[(size_t)Cq * Cq];
__device__ __nv_bfloat16 g_wpl[(size_t)Cq * Cq];

// ---------------------------------------------------------------------------
// Portable PTX helpers (sm_80+: cp.async, ldmatrix, mma.sync)
// ---------------------------------------------------------------------------
__device__ __forceinline__ uint32_t s2u(const void* p) {
    uint32_t a;
    asm("{ .reg .u64 t; cvta.to.shared.u64 t, %1; cvt.u32.u64 %0, t; }"
        : "=r"(a) : "l"(p));
    return a;
}
__device__ __forceinline__ void cp16(uint32_t s, const void* g) {
    asm volatile("cp.async.cg.shared.global [%0], [%1], 16;"
                 :: "r"(s), "l"(g) : "memory");
}
#define CP_COMMIT() asm volatile("cp.async.commit_group;" ::: "memory")
#define CP_WAIT0()  asm volatile("cp.async.wait_group 0;" ::: "memory")
#define CP_WAIT1()  asm volatile("cp.async.wait_group 1;" ::: "memory")

__device__ __forceinline__ void ldsm4(uint32_t* r, uint32_t a) {
    asm volatile("ldmatrix.sync.aligned.m8n8.x4.shared.b16 {%0,%1,%2,%3}, [%4];"
                 : "=r"(r[0]), "=r"(r[1]), "=r"(r[2]), "=r"(r[3]) : "r"(a));
}
__device__ __forceinline__ void ldsm4t(uint32_t* r, uint32_t a) {
    asm volatile("ldmatrix.sync.aligned.m8n8.x4.trans.shared.b16 {%0,%1,%2,%3}, [%4];"
                 : "=r"(r[0]), "=r"(r[1]), "=r"(r[2]), "=r"(r[3]) : "r"(a));
}
__device__ __forceinline__ void mma16816(float* c, const uint32_t* a,
                                         const uint32_t* b) {
    asm volatile("mma.sync.aligned.m16n8k16.row.col.f32.bf16.bf16.f32 "
                 "{%0,%1,%2,%3}, {%4,%5,%6,%7}, {%8,%9}, {%0,%1,%2,%3};"
                 : "+f"(c[0]), "+f"(c[1]), "+f"(c[2]), "+f"(c[3])
                 : "r"(a[0]), "r"(a[1]), "r"(a[2]), "r"(a[3]),
                   "r"(b[0]), "r"(b[1]));
}
// fp32 pair -> packed bf16 hi + packed bf16 residual
__device__ __forceinline__ void split2(float v0, float v1,
                                       uint32_t& h, uint32_t& l) {
    __nv_bfloat162 hh = __floats2bfloat162_rn(v0, v1);
    float r0 = v0 - __bfloat162float(hh.x);
    float r1 = v1 - __bfloat162float(hh.y);
    __nv_bfloat162 ll = __floats2bfloat162_rn(r0, r1);
    h = *(uint32_t*)&hh;
    l = *(uint32_t*)&ll;
}

// ---------------------------------------------------------------------------
// fp32 -> (bf16 hi, bf16 lo) split (inputs x, w_attn, w_proj)
// ---------------------------------------------------------------------------
__global__ void split_kernel(const float* __restrict__ src,
                             __nv_bfloat16* __restrict__ hi,
                             __nv_bfloat16* __restrict__ lo, int n)
{
    int i = (blockIdx.x * blockDim.x + threadIdx.x) * 4;
    if (i >= n) return;
    float4 v = *(const float4*)(src + i);
    uint32_t h0, l0, h1, l1;
    split2(v.x, v.y, h0, l0);
    split2(v.z, v.w, h1, l1);
    uint2 hh = make_uint2(h0, h1), ll = make_uint2(l0, l1);
    *(uint2*)(hi + i) = hh;
    *(uint2*)(lo + i) = ll;
}

// ---------------------------------------------------------------------------
// HMMA GEMM: C = (Ah+Al) @ ((Bh+Bl))^T + bias, split-bf16 3-term, fp32 acc.
// 128x128x32 tile, 3-stage cp.async, 8 warps (4m x 2n), warp tile 32x64.
// SPLIT=1: write bf16 hi/lo pair arrays instead of fp32.
// ---------------------------------------------------------------------------
#define BM 128
#define BN 128
#define BK 32
#define MAT_B   (BM * 64)            // 8192 bytes per matrix tile
#define STAGE_B (4 * MAT_B)          // 32768 (Ah, Al, Bh, Bl)
#define GEMM_SMEM (3 * STAGE_B)      // 98304

template<int SPLIT>
__global__ __launch_bounds__(256, 1)
void gemm_hmma(const __nv_bfloat16* __restrict__ Ah, const __nv_bfloat16* __restrict__ Al,
               const __nv_bfloat16* __restrict__ Bh, const __nv_bfloat16* __restrict__ Bl,
               const float* __restrict__ bias, float* __restrict__ C,
               __nv_bfloat16* __restrict__ Ch, __nv_bfloat16* __restrict__ Cl,
               int M, int N, int K)
{
    extern __shared__ __align__(1024) char smem[];
    const uint32_t sbase = s2u(smem);
    const int tid  = threadIdx.x;
    const int wid  = tid >> 5;
    const int lane = tid & 31;
    const int m0 = blockIdx.y * BM;
    const int n0 = blockIdx.x * BN;
    const int NC = K / BK;

    const int wm = (wid >> 1) * 32;
    const int wn = (wid & 1) * 64;

    const int lrow = tid >> 1;
    const int lcs  = (tid & 1) * 2;
    const uint32_t so0 = lrow * 64 + ((lcs ^ (lrow & 3)) << 4);
    const uint32_t so1 = lrow * 64 + (((lcs + 1) ^ (lrow & 3)) << 4);

    const __nv_bfloat16* gAh = Ah + (size_t)(m0 + lrow) * K + lcs * 8;
    const __nv_bfloat16* gAl = Al + (size_t)(m0 + lrow) * K + lcs * 8;
    const __nv_bfloat16* gBh = Bh + (size_t)(n0 + lrow) * K + lcs * 8;
    const __nv_bfloat16* gBl = Bl + (size_t)(n0 + lrow) * K + lcs * 8;

    auto load_stage = [&](int st, int c) {
        const uint32_t sb = sbase + st * STAGE_B;
        const int off = c * BK;
        cp16(sb + so0,           gAh + off);
        cp16(sb + so1,           gAh + off + 8);
        cp16(sb + MAT_B + so0,   gAl + off);
        cp16(sb + MAT_B + so1,   gAl + off + 8);
        cp16(sb + 2*MAT_B + so0, gBh + off);
        cp16(sb + 2*MAT_B + so1, gBh + off + 8);
        cp16(sb + 3*MAT_B + so0, gBl + off);
        cp16(sb + 3*MAT_B + so1, gBl + off + 8);
    };

    float acc[2][8][4];
#pragma unroll
    for (int i = 0; i < 2; i++)
#pragma unroll
        for (int j = 0; j < 8; j++)
#pragma unroll
            for (int k = 0; k < 4; k++) acc[i][j][k] = 0.f;

    const int g   = lane >> 3;
    const int l7  = lane & 7;
    const int arow = wm + (g & 1) * 8 + l7;
    const int achk = g >> 1;
    const int brow = wn + ((g & 2) << 2) + l7;
    const int bchk = g & 1;

    load_stage(0, 0); CP_COMMIT();
    load_stage(1, 1); CP_COMMIT();

    for (int c = 0; c < NC; c++) {
        const int st = c % 3;
        CP_WAIT1();
        __syncthreads();

        if (c + 2 < NC) load_stage((c + 2) % 3, c + 2);
        CP_COMMIT();

        const uint32_t sb  = sbase + st * STAGE_B;
        const uint32_t sAh = sb;
        const uint32_t sAl = sb + MAT_B;
        const uint32_t sBh = sb + 2 * MAT_B;
        const uint32_t sBl = sb + 3 * MAT_B;

#pragma unroll
        for (int s = 0; s < 2; s++) {
            uint32_t ah[2][4], al[2][4];
#pragma unroll
            for (int mt = 0; mt < 2; mt++) {
                const int r = arow + mt * 16;
                const int ck = achk + 2 * s;
                const uint32_t ad = r * 64 + ((ck ^ (r & 3)) << 4);
                ldsm4(ah[mt], sAh + ad);
                ldsm4(al[mt], sAl + ad);
            }
#pragma unroll
            for (int ng = 0; ng < 4; ng++) {
                const int r = brow + ng * 16;
                const int ck = bchk + 2 * s;
                const uint32_t bd = r * 64 + ((ck ^ (r & 3)) << 4);
                uint32_t bh[4], bl[4];
                ldsm4(bh, sBh + bd);
                ldsm4(bl, sBl + bd);
#pragma unroll
                for (int mt = 0; mt < 2; mt++) {
                    mma16816(acc[mt][2*ng],   ah[mt], bh);
                    mma16816(acc[mt][2*ng+1], ah[mt], bh + 2);
                    mma16816(acc[mt][2*ng],   ah[mt], bl);
                    mma16816(acc[mt][2*ng+1], ah[mt], bl + 2);
                    mma16816(acc[mt][2*ng],   al[mt], bh);
                    mma16816(acc[mt][2*ng+1], al[mt], bh + 2);
                }
            }
        }
        __syncthreads();
    }

    const int r = lane >> 2;
    const int t = lane & 3;
#pragma unroll
    for (int nt = 0; nt < 8; nt++) {
        const int col = n0 + wn + nt * 8 + t * 2;
        const float2 bv = *(const float2*)(bias + col);
#pragma unroll
        for (int mt = 0; mt < 2; mt++) {
            const int row0 = m0 + wm + mt * 16 + r;
            float v0 = acc[mt][nt][0] + bv.x, v1 = acc[mt][nt][1] + bv.y;
            float v2 = acc[mt][nt][2] + bv.x, v3 = acc[mt][nt][3] + bv.y;
            if (SPLIT) {
                uint32_t h01, l01, h23, l23;
                split2(v0, v1, h01, l01);
                split2(v2, v3, h23, l23);
                *(uint32_t*)(Ch + (size_t)row0 * N + col)       = h01;
                *(uint32_t*)(Cl + (size_t)row0 * N + col)       = l01;
                *(uint32_t*)(Ch + (size_t)(row0 + 8) * N + col) = h23;
                *(uint32_t*)(Cl + (size_t)(row0 + 8) * N + col) = l23;
            } else {
                *(float2*)(C + (size_t)row0 * N + col)       = make_float2(v0, v1);
                *(float2*)(C + (size_t)(row0 + 8) * N + col) = make_float2(v2, v3);
            }
        }
    }
}

// ---------------------------------------------------------------------------
// Tensorized flash attention (causal), split-bf16 HMMA, fp32 softmax.
// BQ=128, BKV=64, 8 warps (16 q-rows each), double-buffered K/V tiles.
// Reads split qkv (qkvh/qkvl), writes split y (yh/yl).
// ---------------------------------------------------------------------------
#define FQ_B   16384                 // Q tile hi or lo: 128 rows x 128 B
#define FKV_B  8192                  // one K or V tile: 64 rows x 128 B
#define FSTG_B (4 * FKV_B)           // Kh, Kl, Vh, Vl
#define FLASH_SMEM (2 * FQ_B + 2 * FSTG_B)   // 98304

__global__ __launch_bounds__(256, 1)
void flash_hmma(const __nv_bfloat16* __restrict__ qkvh,
                const __nv_bfloat16* __restrict__ qkvl,
                __nv_bfloat16* __restrict__ yh,
                __nv_bfloat16* __restrict__ yl)
{
    extern __shared__ __align__(1024) char smem[];
    const uint32_t sbase = s2u(smem);
    const uint32_t sQh = sbase;
    const uint32_t sQl = sbase + FQ_B;

    const int tid  = threadIdx.x;
    const int wq   = tid >> 5;            // warp: q rows wq*16..+15
    const int lane = tid & 31;
    const int qt   = gridDim.x - 1 - blockIdx.x;   // heavy CTAs first
    const int bh   = blockIdx.y;
    const int b    = bh >> 4;
    const int h    = bh & 15;
    const int q0   = qt * 128;
    const int jtmax = 2 * qt + 1;

    const int g  = lane >> 3;
    const int l7 = lane & 7;
    const int r  = lane >> 2;
    const int t  = lane & 3;

    // ---- load Q tile (hi+lo) ----
    {
        const int row = tid >> 1;
        const int cb  = (tid & 1) * 4;
        const size_t gb = (size_t)(b * Tq + q0 + row) * C3 + h * Dq;
#pragma unroll
        for (int u = 0; u < 4; u++) {
            const int c = cb + u;
            const uint32_t off = row * 128 + ((c ^ (row & 7)) << 4);
            cp16(sQh + off, qkvh + gb + c * 8);
            cp16(sQl + off, qkvl + gb + c * 8);
        }
    }
    // ---- load K/V tile 0 into stage 0 ----
    auto load_kv = [&](int jt, int s) {
        const uint32_t st = sbase + 2 * FQ_B + s * FSTG_B;
#pragma unroll
        for (int u = 0; u < 2; u++) {
            const int idx = tid * 2 + u;
            const int row = idx >> 3;
            const int c   = idx & 7;
            const uint32_t off = row * 128 + ((c ^ (row & 7)) << 4);
            const size_t gk = (size_t)(b * Tq + jt * 64 + row) * C3 + Cq + h * Dq + c * 8;
            const size_t gv = gk + Cq;
            cp16(st + off,             qkvh + gk);
            cp16(st + FKV_B + off,     qkvl + gk);
            cp16(st + 2*FKV_B + off,   qkvh + gv);
            cp16(st + 3*FKV_B + off,   qkvl + gv);
        }
    };
    load_kv(0, 0);
    CP_COMMIT();
    CP_WAIT0();
    __syncthreads();

    // ---- Q fragments (registers, 4 k-chunks x 4 regs, hi+lo) ----
    uint32_t qhf[4][4], qlf[4][4];
    {
        const int arow = wq * 16 + (g & 1) * 8 + l7;
#pragma unroll
        for (int kc = 0; kc < 4; kc++) {
            const int ck = 2 * kc + (g >> 1);
            const uint32_t ad = arow * 128 + ((ck ^ (arow & 7)) << 4);
            ldsm4(qhf[kc], sQh + ad);
            ldsm4(qlf[kc], sQl + ad);
        }
    }

    float oacc[8][4];
#pragma unroll
    for (int i = 0; i < 8; i++)
#pragma unroll
        for (int j = 0; j < 4; j++) oacc[i][j] = 0.f;
    float m0r = -1e30f, m1r = -1e30f, l0r = 0.f, l1r = 0.f;

    const int qr0 = q0 + wq * 16 + r;   // this lane's first q row
    const int kmax_w = q0 + wq * 16 + 15;

    for (int jt = 0; jt <= jtmax; jt++) {
        const int s = jt & 1;
        const int k0 = jt * 64;
        if (jt > 0) CP_WAIT0();
        __syncthreads();
        if (jt < jtmax) { load_kv(jt + 1, s ^ 1); CP_COMMIT(); }

        if (k0 <= kmax_w) {
            const uint32_t st  = sbase + 2 * FQ_B + s * FSTG_B;
            const uint32_t sKh = st;
            const uint32_t sKl = st + FKV_B;
            const uint32_t sVh = st + 2 * FKV_B;
            const uint32_t sVl = st + 3 * FKV_B;

            // ---- S = Q K^T (split, fp32 acc) ----
            float sacc[8][4];
#pragma unroll
            for (int i = 0; i < 8; i++)
#pragma unroll
                for (int j = 0; j < 4; j++) sacc[i][j] = 0.f;

#pragma unroll
            for (int ntp = 0; ntp < 4; ntp++) {
                const int krow = ntp * 16 + ((g & 2) << 2) + l7;
#pragma unroll
                for (int kc = 0; kc < 4; kc++) {
                    const int ck = 2 * kc + (g & 1);
                    const uint32_t kd = krow * 128 + ((ck ^ (krow & 7)) << 4);
                    uint32_t kh[4], kl[4];
                    ldsm4(kh, sKh + kd);
                    ldsm4(kl, sKl + kd);
                    mma16816(sacc[2*ntp],   qhf[kc], kh);
                    mma16816(sacc[2*ntp+1], qhf[kc], kh + 2);
                    mma16816(sacc[2*ntp],   qhf[kc], kl);
                    mma16816(sacc[2*ntp+1], qhf[kc], kl + 2);
                    mma16816(sacc[2*ntp],   qlf[kc], kh);
                    mma16816(sacc[2*ntp+1], qlf[kc], kh + 2);
                }
            }

            // ---- scale + causal mask ----
            const bool need_mask = (k0 + 63 > q0 + wq * 16);
#pragma unroll
            for (int nt = 0; nt < 8; nt++) {
#pragma unroll
                for (int j = 0; j < 4; j++) sacc[nt][j] *= 0.125f;
                if (need_mask) {
                    const int col = k0 + nt * 8 + 2 * t;
                    if (col     > qr0)     sacc[nt][0] = -1e30f;
                    if (col + 1 > qr0)     sacc[nt][1] = -1e30f;
                    if (col     > qr0 + 8) sacc[nt][2] = -1e30f;
                    if (col + 1 > qr0 + 8) sacc[nt][3] = -1e30f;
                }
            }

            // ---- online softmax ----
            float mx0 = -1e30f, mx1 = -1e30f;
#pragma unroll
            for (int nt = 0; nt < 8; nt++) {
                mx0 = fmaxf(mx0, fmaxf(sacc[nt][0], sacc[nt][1]));
                mx1 = fmaxf(mx1, fmaxf(sacc[nt][2], sacc[nt][3]));
            }
            mx0 = fmaxf(mx0, __shfl_xor_sync(0xffffffffu, mx0, 1));
            mx0 = fmaxf(mx0, __shfl_xor_sync(0xffffffffu, mx0, 2));
            mx1 = fmaxf(mx1, __shfl_xor_sync(0xffffffffu, mx1, 1));
            mx1 = fmaxf(mx1, __shfl_xor_sync(0xffffffffu, mx1, 2));
            const float mn0 = fmaxf(m0r, mx0);
            const float mn1 = fmaxf(m1r, mx1);
            const float al0 = __expf(m0r - mn0);
            const float al1 = __expf(m1r - mn1);
            m0r = mn0; m1r = mn1;

            float rs0 = 0.f, rs1 = 0.f;
#pragma unroll
            for (int nt = 0; nt < 8; nt++) {
                sacc[nt][0] = __expf(sacc[nt][0] - mn0);
                sacc[nt][1] = __expf(sacc[nt][1] - mn0);
                sacc[nt][2] = __expf(sacc[nt][2] - mn1);
                sacc[nt][3] = __expf(sacc[nt][3] - mn1);
                rs0 += sacc[nt][0] + sacc[nt][1];
                rs1 += sacc[nt][2] + sacc[nt][3];
            }
            rs0 += __shfl_xor_sync(0xffffffffu, rs0, 1);
            rs0 += __shfl_xor_sync(0xffffffffu, rs0, 2);
            rs1 += __shfl_xor_sync(0xffffffffu, rs1, 1);
            rs1 += __shfl_xor_sync(0xffffffffu, rs1, 2);
            l0r = l0r * al0 + rs0;
            l1r = l1r * al1 + rs1;
#pragma unroll
            for (int nt = 0; nt < 8; nt++) {
                oacc[nt][0] *= al0; oacc[nt][1] *= al0;
                oacc[nt][2] *= al1; oacc[nt][3] *= al1;
            }

            // ---- P fragments (split bf16, A-fragment layout) ----
            uint32_t ph[4][4], pl[4][4];
#pragma unroll
            for (int kc = 0; kc < 4; kc++) {
                split2(sacc[2*kc][0],   sacc[2*kc][1],   ph[kc][0], pl[kc][0]);
                split2(sacc[2*kc][2],   sacc[2*kc][3],   ph[kc][1], pl[kc][1]);
                split2(sacc[2*kc+1][0], sacc[2*kc+1][1], ph[kc][2], pl[kc][2]);
                split2(sacc[2*kc+1][2], sacc[2*kc+1][3], ph[kc][3], pl[kc][3]);
            }

            // ---- O += P V (split) ----
#pragma unroll
            for (int ntp = 0; ntp < 4; ntp++) {
#pragma unroll
                for (int kc = 0; kc < 4; kc++) {
                    const int vrow = kc * 16 + ((g & 1) << 3) + l7;
                    const int vc   = 2 * ntp + (g >> 1);
                    const uint32_t vd = vrow * 128 + ((vc ^ (vrow & 7)) << 4);
                    uint32_t vh[4], vl[4];
                    ldsm4t(vh, sVh + vd);
                    ldsm4t(vl, sVl + vd);
                    mma16816(oacc[2*ntp],   ph[kc], vh);
                    mma16816(oacc[2*ntp+1], ph[kc], vh + 2);
                    mma16816(oacc[2*ntp],   ph[kc], vl);
                    mma16816(oacc[2*ntp+1], ph[kc], vl + 2);
                    mma16816(oacc[2*ntp],   pl[kc], vh);
                    mma16816(oacc[2*ntp+1], pl[kc], vh + 2);
                }
            }
        }
    }

    // ---- epilogue: normalize, split-write y ----
    const float inv0 = 1.f / l0r;
    const float inv1 = 1.f / l1r;
    const size_t tok0 = (size_t)(b * Tq + q0 + wq * 16 + r);
    const size_t tok1 = tok0 + 8;
#pragma unroll
    for (int nt = 0; nt < 8; nt++) {
        const int col = h * Dq + nt * 8 + 2 * t;
        uint32_t h01, l01, h23, l23;
        split2(oacc[nt][0] * inv0, oacc[nt][1] * inv0, h01, l01);
        split2(oacc[nt][2] * inv1, oacc[nt][3] * inv1, h23, l23);
        *(uint32_t*)(yh + tok0 * Cq + col) = h01;
        *(uint32_t*)(yl + tok0 * Cq + col) = l01;
        *(uint32_t*)(yh + tok1 * Cq + col) = h23;
        *(uint32_t*)(yl + tok1 * Cq + col) = l23;
    }
}

// ---------------------------------------------------------------------------
extern "C" void kernel_launch(void* const* d_in, const int* in_sizes, int n_in,
                              void* d_out, int out_size)
{
    const float* x      = (const float*)d_in[0];
    const float* w_attn = (const float*)d_in[1];
    const float* b_attn = (const float*)d_in[2];
    const float* w_proj = (const float*)d_in[3];
    const float* b_proj = (const float*)d_in[4];
    float* out = (float*)d_out;

    __nv_bfloat16 *qkvh, *qkvl, *xh, *xl, *wah, *wal, *yh, *yl, *wph, *wpl;
    cudaGetSymbolAddress((void**)&qkvh, g_qkvh);
    cudaGetSymbolAddress((void**)&qkvl, g_qkvl);
    cudaGetSymbolAddress((void**)&xh,  g_xh);
    cudaGetSymbolAddress((void**)&xl,  g_xl);
    cudaGetSymbolAddress((void**)&wah, g_wah);
    cudaGetSymbolAddress((void**)&wal, g_wal);
    cudaGetSymbolAddress((void**)&yh,  g_yh);
    cudaGetSymbolAddress((void**)&yl,  g_yl);
    cudaGetSymbolAddress((void**)&wph, g_wph);
    cudaGetSymbolAddress((void**)&wpl, g_wpl);

    cudaFuncSetAttribute(gemm_hmma<0>,
                         cudaFuncAttributeMaxDynamicSharedMemorySize, GEMM_SMEM);
    cudaFuncSetAttribute(gemm_hmma<1>,
                         cudaFuncAttributeMaxDynamicSharedMemorySize, GEMM_SMEM);
    cudaFuncSetAttribute(flash_hmma,
                         cudaFuncAttributeMaxDynamicSharedMemorySize, FLASH_SMEM);

    // splits (fp32 -> bf16 hi/lo) for x and weights
    {
        int n1 = NTOK * Cq;
        split_kernel<<<(n1 / 4 + 255) / 256, 256>>>(x, xh, xl, n1);
        int n2 = C3 * Cq;
        split_kernel<<<(n2 / 4 + 255) / 256, 256>>>(w_attn, wah, wal, n2);
        int n3 = Cq * Cq;
        split_kernel<<<(n3 / 4 + 255) / 256, 256>>>(w_proj, wph, wpl, n3);
    }

    // 1) qkv = x @ w_attn^T + b_attn  -> split bf16 directly
    {
        dim3 grid(C3 / BN, NTOK / BM);
        gemm_hmma<1><<<grid, 256, GEMM_SMEM>>>(xh, xl, wah, wal, b_attn,
                                               nullptr, qkvh, qkvl,
                                               NTOK, C3, Cq);
    }
    // 2) tensorized flash attention -> split y
    {
        dim3 grid(Tq / 128, Bq * Hq);
        flash_hmma<<<grid, 256, FLASH_SMEM>>>(qkvh, qkvl, yh, yl);
    }
    // 3) out = y @ w_proj^T + b_proj  (fp32 out)
    {
        dim3 grid(Cq / BN, NTOK / BM);
        gemm_hmma<0><<<grid, 256, GEMM_SMEM>>>(yh, yl, wph, wpl, b_proj,
                                               out, nullptr, nullptr,
                                               NTOK, Cq, Cq);
    }
}

// round 6
// speedup vs baseline: 2.6912x; 1.6568x over previous
#include <cuda_runtime.h>
#include <cuda_bf16.h>
#include <math.h>
#include <stdint.h>

// Problem constants
#define Bq   4
#define Tq   2048
#define Cq   1024
#define Hq   16
#define Dq   64
#define NTOK (Bq * Tq)        // 8192
#define C3   (3 * Cq)         // 3072

// ---------------------------------------------------------------------------
// Scratch (allocation-free rule: __device__ globals)
// ---------------------------------------------------------------------------
__device__ __nv_bfloat16 g_qkvh[(size_t)NTOK * C3];
__device__ __nv_bfloat16 g_qkvl[(size_t)NTOK * C3];
__device__ __nv_bfloat16 g_xh[(size_t)NTOK * Cq];
__device__ __nv_bfloat16 g_xl[(size_t)NTOK * Cq];
__device__ __nv_bfloat16 g_wah[(size_t)C3 * Cq];
__device__ __nv_bfloat16 g_wal[(size_t)C3 * Cq];
__device__ __nv_bfloat16 g_yh[(size_t)NTOK * Cq];
__device__ __nv_bfloat16 g_yl[(size_t)NTOK * Cq];
__device__ __nv_bfloat16 g_wph[(size_t)Cq * Cq];
__device__ __nv_bfloat16 g_wpl[(size_t)Cq * Cq];

// ---------------------------------------------------------------------------
// Portable PTX helpers (sm_80+: cp.async, ldmatrix, mma.sync)
// ---------------------------------------------------------------------------
__device__ __forceinline__ uint32_t s2u(const void* p) {
    uint32_t a;
    asm("{ .reg .u64 t; cvta.to.shared.u64 t, %1; cvt.u32.u64 %0, t; }"
        : "=r"(a) : "l"(p));
    return a;
}
__device__ __forceinline__ void cp16(uint32_t s, const void* g) {
    asm volatile("cp.async.cg.shared.global [%0], [%1], 16;"
                 :: "r"(s), "l"(g) : "memory");
}
#define CP_COMMIT() asm volatile("cp.async.commit_group;" ::: "memory")
#define CP_WAIT0()  asm volatile("cp.async.wait_group 0;" ::: "memory")
#define CP_WAIT1()  asm volatile("cp.async.wait_group 1;" ::: "memory")

__device__ __forceinline__ void ldsm4(uint32_t* r, uint32_t a) {
    asm volatile("ldmatrix.sync.aligned.m8n8.x4.shared.b16 {%0,%1,%2,%3}, [%4];"
                 : "=r"(r[0]), "=r"(r[1]), "=r"(r[2]), "=r"(r[3]) : "r"(a));
}
__device__ __forceinline__ void ldsm4t(uint32_t* r, uint32_t a) {
    asm volatile("ldmatrix.sync.aligned.m8n8.x4.trans.shared.b16 {%0,%1,%2,%3}, [%4];"
                 : "=r"(r[0]), "=r"(r[1]), "=r"(r[2]), "=r"(r[3]) : "r"(a));
}
__device__ __forceinline__ void mma16816(float* c, const uint32_t* a,
                                         const uint32_t* b) {
    asm volatile("mma.sync.aligned.m16n8k16.row.col.f32.bf16.bf16.f32 "
                 "{%0,%1,%2,%3}, {%4,%5,%6,%7}, {%8,%9}, {%0,%1,%2,%3};"
                 : "+f"(c[0]), "+f"(c[1]), "+f"(c[2]), "+f"(c[3])
                 : "r"(a[0]), "r"(a[1]), "r"(a[2]), "r"(a[3]),
                   "r"(b[0]), "r"(b[1]));
}
// fp32 pair -> packed bf16 hi + packed bf16 residual
__device__ __forceinline__ void split2(float v0, float v1,
                                       uint32_t& h, uint32_t& l) {
    __nv_bfloat162 hh = __floats2bfloat162_rn(v0, v1);
    float r0 = v0 - __bfloat162float(hh.x);
    float r1 = v1 - __bfloat162float(hh.y);
    __nv_bfloat162 ll = __floats2bfloat162_rn(r0, r1);
    h = *(uint32_t*)&hh;
    l = *(uint32_t*)&ll;
}

// ---------------------------------------------------------------------------
// fp32 -> (bf16 hi, bf16 lo) split (inputs x, w_attn, w_proj)
// ---------------------------------------------------------------------------
__global__ void split_kernel(const float* __restrict__ src,
                             __nv_bfloat16* __restrict__ hi,
                             __nv_bfloat16* __restrict__ lo, int n)
{
    int i = (blockIdx.x * blockDim.x + threadIdx.x) * 4;
    if (i >= n) return;
    float4 v = *(const float4*)(src + i);
    uint32_t h0, l0, h1, l1;
    split2(v.x, v.y, h0, l0);
    split2(v.z, v.w, h1, l1);
    uint2 hh = make_uint2(h0, h1), ll = make_uint2(l0, l1);
    *(uint2*)(hi + i) = hh;
    *(uint2*)(lo + i) = ll;
}

// ---------------------------------------------------------------------------
// HMMA GEMM: C = (Ah+Al) @ ((Bh+Bl))^T + bias, split-bf16 3-term, fp32 acc.
// 128x128x32 tile, 3-stage cp.async, 8 warps (4m x 2n), warp tile 32x64.
// __launch_bounds__(256, 2): cap regs at 128 so TWO CTAs fit per SM
// (smem 2x96KB = 192KB <= 227KB) — second CTA hides sync/load phases.
// SPLIT=1: write bf16 hi/lo pair arrays instead of fp32.
// ---------------------------------------------------------------------------
#define BM 128
#define BN 128
#define BK 32
#define MAT_B   (BM * 64)            // 8192 bytes per matrix tile
#define STAGE_B (4 * MAT_B)          // 32768 (Ah, Al, Bh, Bl)
#define GEMM_SMEM (3 * STAGE_B)      // 98304

template<int SPLIT>
__global__ __launch_bounds__(256, 2)
void gemm_hmma(const __nv_bfloat16* __restrict__ Ah, const __nv_bfloat16* __restrict__ Al,
               const __nv_bfloat16* __restrict__ Bh, const __nv_bfloat16* __restrict__ Bl,
               const float* __restrict__ bias, float* __restrict__ C,
               __nv_bfloat16* __restrict__ Ch, __nv_bfloat16* __restrict__ Cl,
               int M, int N, int K)
{
    extern __shared__ __align__(1024) char smem[];
    const uint32_t sbase = s2u(smem);
    const int tid  = threadIdx.x;
    const int wid  = tid >> 5;
    const int lane = tid & 31;
    const int m0 = blockIdx.y * BM;
    const int n0 = blockIdx.x * BN;
    const int NC = K / BK;

    const int wm = (wid >> 1) * 32;
    const int wn = (wid & 1) * 64;

    const int lrow = tid >> 1;
    const int lcs  = (tid & 1) * 2;
    const uint32_t so0 = lrow * 64 + ((lcs ^ (lrow & 3)) << 4);
    const uint32_t so1 = lrow * 64 + (((lcs + 1) ^ (lrow & 3)) << 4);

    const __nv_bfloat16* gAh = Ah + (size_t)(m0 + lrow) * K + lcs * 8;
    const __nv_bfloat16* gAl = Al + (size_t)(m0 + lrow) * K + lcs * 8;
    const __nv_bfloat16* gBh = Bh + (size_t)(n0 + lrow) * K + lcs * 8;
    const __nv_bfloat16* gBl = Bl + (size_t)(n0 + lrow) * K + lcs * 8;

    auto load_stage = [&](int st, int c) {
        const uint32_t sb = sbase + st * STAGE_B;
        const int off = c * BK;
        cp16(sb + so0,           gAh + off);
        cp16(sb + so1,           gAh + off + 8);
        cp16(sb + MAT_B + so0,   gAl + off);
        cp16(sb + MAT_B + so1,   gAl + off + 8);
        cp16(sb + 2*MAT_B + so0, gBh + off);
        cp16(sb + 2*MAT_B + so1, gBh + off + 8);
        cp16(sb + 3*MAT_B + so0, gBl + off);
        cp16(sb + 3*MAT_B + so1, gBl + off + 8);
    };

    float acc[2][8][4];
#pragma unroll
    for (int i = 0; i < 2; i++)
#pragma unroll
        for (int j = 0; j < 8; j++)
#pragma unroll
            for (int k = 0; k < 4; k++) acc[i][j][k] = 0.f;

    const int g   = lane >> 3;
    const int l7  = lane & 7;
    const int arow = wm + (g & 1) * 8 + l7;
    const int achk = g >> 1;
    const int brow = wn + ((g & 2) << 2) + l7;
    const int bchk = g & 1;

    load_stage(0, 0); CP_COMMIT();
    load_stage(1, 1); CP_COMMIT();

    for (int c = 0; c < NC; c++) {
        const int st = c % 3;
        CP_WAIT1();
        __syncthreads();

        if (c + 2 < NC) load_stage((c + 2) % 3, c + 2);
        CP_COMMIT();

        const uint32_t sb  = sbase + st * STAGE_B;
        const uint32_t sAh = sb;
        const uint32_t sAl = sb + MAT_B;
        const uint32_t sBh = sb + 2 * MAT_B;
        const uint32_t sBl = sb + 3 * MAT_B;

#pragma unroll
        for (int s = 0; s < 2; s++) {
            uint32_t ah[2][4], al[2][4];
#pragma unroll
            for (int mt = 0; mt < 2; mt++) {
                const int r = arow + mt * 16;
                const int ck = achk + 2 * s;
                const uint32_t ad = r * 64 + ((ck ^ (r & 3)) << 4);
                ldsm4(ah[mt], sAh + ad);
                ldsm4(al[mt], sAl + ad);
            }
#pragma unroll
            for (int ng = 0; ng < 4; ng++) {
                const int r = brow + ng * 16;
                const int ck = bchk + 2 * s;
                const uint32_t bd = r * 64 + ((ck ^ (r & 3)) << 4);
                uint32_t bh[4], bl[4];
                ldsm4(bh, sBh + bd);
                ldsm4(bl, sBl + bd);
#pragma unroll
                for (int mt = 0; mt < 2; mt++) {
                    mma16816(acc[mt][2*ng],   ah[mt], bh);
                    mma16816(acc[mt][2*ng+1], ah[mt], bh + 2);
                    mma16816(acc[mt][2*ng],   ah[mt], bl);
                    mma16816(acc[mt][2*ng+1], ah[mt], bl + 2);
                    mma16816(acc[mt][2*ng],   al[mt], bh);
                    mma16816(acc[mt][2*ng+1], al[mt], bh + 2);
                }
            }
        }
        __syncthreads();
    }

    const int r = lane >> 2;
    const int t = lane & 3;
#pragma unroll
    for (int nt = 0; nt < 8; nt++) {
        const int col = n0 + wn + nt * 8 + t * 2;
        const float2 bv = *(const float2*)(bias + col);
#pragma unroll
        for (int mt = 0; mt < 2; mt++) {
            const int row0 = m0 + wm + mt * 16 + r;
            float v0 = acc[mt][nt][0] + bv.x, v1 = acc[mt][nt][1] + bv.y;
            float v2 = acc[mt][nt][2] + bv.x, v3 = acc[mt][nt][3] + bv.y;
            if (SPLIT) {
                uint32_t h01, l01, h23, l23;
                split2(v0, v1, h01, l01);
                split2(v2, v3, h23, l23);
                *(uint32_t*)(Ch + (size_t)row0 * N + col)       = h01;
                *(uint32_t*)(Cl + (size_t)row0 * N + col)       = l01;
                *(uint32_t*)(Ch + (size_t)(row0 + 8) * N + col) = h23;
                *(uint32_t*)(Cl + (size_t)(row0 + 8) * N + col) = l23;
            } else {
                *(float2*)(C + (size_t)row0 * N + col)       = make_float2(v0, v1);
                *(float2*)(C + (size_t)(row0 + 8) * N + col) = make_float2(v2, v3);
            }
        }
    }
}

// ---------------------------------------------------------------------------
// Tensorized flash attention (causal), split-bf16 HMMA, fp32 softmax.
// BQ=128, BKV=64, 8 warps (16 q-rows each), double-buffered K/V tiles.
// Reads split qkv (qkvh/qkvl), writes split y (yh/yl).
// ---------------------------------------------------------------------------
#define FQ_B   16384                 // Q tile hi or lo: 128 rows x 128 B
#define FKV_B  8192                  // one K or V tile: 64 rows x 128 B
#define FSTG_B (4 * FKV_B)           // Kh, Kl, Vh, Vl
#define FLASH_SMEM (2 * FQ_B + 2 * FSTG_B)   // 98304

__global__ __launch_bounds__(256, 1)
void flash_hmma(const __nv_bfloat16* __restrict__ qkvh,
                const __nv_bfloat16* __restrict__ qkvl,
                __nv_bfloat16* __restrict__ yh,
                __nv_bfloat16* __restrict__ yl)
{
    extern __shared__ __align__(1024) char smem[];
    const uint32_t sbase = s2u(smem);
    const uint32_t sQh = sbase;
    const uint32_t sQl = sbase + FQ_B;

    const int tid  = threadIdx.x;
    const int wq   = tid >> 5;            // warp: q rows wq*16..+15
    const int lane = tid & 31;
    const int qt   = gridDim.x - 1 - blockIdx.x;   // heavy CTAs first
    const int bh   = blockIdx.y;
    const int b    = bh >> 4;
    const int h    = bh & 15;
    const int q0   = qt * 128;
    const int jtmax = 2 * qt + 1;

    const int g  = lane >> 3;
    const int l7 = lane & 7;
    const int r  = lane >> 2;
    const int t  = lane & 3;

    // ---- load Q tile (hi+lo) ----
    {
        const int row = tid >> 1;
        const int cb  = (tid & 1) * 4;
        const size_t gb = (size_t)(b * Tq + q0 + row) * C3 + h * Dq;
#pragma unroll
        for (int u = 0; u < 4; u++) {
            const int c = cb + u;
            const uint32_t off = row * 128 + ((c ^ (row & 7)) << 4);
            cp16(sQh + off, qkvh + gb + c * 8);
            cp16(sQl + off, qkvl + gb + c * 8);
        }
    }
    // ---- load K/V tile into stage s ----
    auto load_kv = [&](int jt, int s) {
        const uint32_t st = sbase + 2 * FQ_B + s * FSTG_B;
#pragma unroll
        for (int u = 0; u < 2; u++) {
            const int idx = tid * 2 + u;
            const int row = idx >> 3;
            const int c   = idx & 7;
            const uint32_t off = row * 128 + ((c ^ (row & 7)) << 4);
            const size_t gk = (size_t)(b * Tq + jt * 64 + row) * C3 + Cq + h * Dq + c * 8;
            const size_t gv = gk + Cq;
            cp16(st + off,             qkvh + gk);
            cp16(st + FKV_B + off,     qkvl + gk);
            cp16(st + 2*FKV_B + off,   qkvh + gv);
            cp16(st + 3*FKV_B + off,   qkvl + gv);
        }
    };
    load_kv(0, 0);
    CP_COMMIT();
    CP_WAIT0();
    __syncthreads();

    // ---- Q fragments (registers, 4 k-chunks x 4 regs, hi+lo) ----
    uint32_t qhf[4][4], qlf[4][4];
    {
        const int arow = wq * 16 + (g & 1) * 8 + l7;
#pragma unroll
        for (int kc = 0; kc < 4; kc++) {
            const int ck = 2 * kc + (g >> 1);
            const uint32_t ad = arow * 128 + ((ck ^ (arow & 7)) << 4);
            ldsm4(qhf[kc], sQh + ad);
            ldsm4(qlf[kc], sQl + ad);
        }
    }

    float oacc[8][4];
#pragma unroll
    for (int i = 0; i < 8; i++)
#pragma unroll
        for (int j = 0; j < 4; j++) oacc[i][j] = 0.f;
    float m0r = -1e30f, m1r = -1e30f, l0r = 0.f, l1r = 0.f;

    const int qr0 = q0 + wq * 16 + r;   // this lane's first q row
    const int kmax_w = q0 + wq * 16 + 15;

    for (int jt = 0; jt <= jtmax; jt++) {
        const int s = jt & 1;
        const int k0 = jt * 64;
        if (jt > 0) CP_WAIT0();
        __syncthreads();
        if (jt < jtmax) { load_kv(jt + 1, s ^ 1); CP_COMMIT(); }

        if (k0 <= kmax_w) {
            const uint32_t st  = sbase + 2 * FQ_B + s * FSTG_B;
            const uint32_t sKh = st;
            const uint32_t sKl = st + FKV_B;
            const uint32_t sVh = st + 2 * FKV_B;
            const uint32_t sVl = st + 3 * FKV_B;

            // ---- S = Q K^T (split, fp32 acc) ----
            float sacc[8][4];
#pragma unroll
            for (int i = 0; i < 8; i++)
#pragma unroll
                for (int j = 0; j < 4; j++) sacc[i][j] = 0.f;

#pragma unroll
            for (int ntp = 0; ntp < 4; ntp++) {
                const int krow = ntp * 16 + ((g & 2) << 2) + l7;
#pragma unroll
                for (int kc = 0; kc < 4; kc++) {
                    const int ck = 2 * kc + (g & 1);
                    const uint32_t kd = krow * 128 + ((ck ^ (krow & 7)) << 4);
                    uint32_t kh[4], kl[4];
                    ldsm4(kh, sKh + kd);
                    ldsm4(kl, sKl + kd);
                    mma16816(sacc[2*ntp],   qhf[kc], kh);
                    mma16816(sacc[2*ntp+1], qhf[kc], kh + 2);
                    mma16816(sacc[2*ntp],   qhf[kc], kl);
                    mma16816(sacc[2*ntp+1], qhf[kc], kl + 2);
                    mma16816(sacc[2*ntp],   qlf[kc], kh);
                    mma16816(sacc[2*ntp+1], qlf[kc], kh + 2);
                }
            }

            // ---- scale + causal mask ----
            const bool need_mask = (k0 + 63 > q0 + wq * 16);
#pragma unroll
            for (int nt = 0; nt < 8; nt++) {
#pragma unroll
                for (int j = 0; j < 4; j++) sacc[nt][j] *= 0.125f;
                if (need_mask) {
                    const int col = k0 + nt * 8 + 2 * t;
                    if (col     > qr0)     sacc[nt][0] = -1e30f;
                    if (col + 1 > qr0)     sacc[nt][1] = -1e30f;
                    if (col     > qr0 + 8) sacc[nt][2] = -1e30f;
                    if (col + 1 > qr0 + 8) sacc[nt][3] = -1e30f;
                }
            }

            // ---- online softmax ----
            float mx0 = -1e30f, mx1 = -1e30f;
#pragma unroll
            for (int nt = 0; nt < 8; nt++) {
                mx0 = fmaxf(mx0, fmaxf(sacc[nt][0], sacc[nt][1]));
                mx1 = fmaxf(mx1, fmaxf(sacc[nt][2], sacc[nt][3]));
            }
            mx0 = fmaxf(mx0, __shfl_xor_sync(0xffffffffu, mx0, 1));
            mx0 = fmaxf(mx0, __shfl_xor_sync(0xffffffffu, mx0, 2));
            mx1 = fmaxf(mx1, __shfl_xor_sync(0xffffffffu, mx1, 1));
            mx1 = fmaxf(mx1, __shfl_xor_sync(0xffffffffu, mx1, 2));
            const float mn0 = fmaxf(m0r, mx0);
            const float mn1 = fmaxf(m1r, mx1);
            const float al0 = __expf(m0r - mn0);
            const float al1 = __expf(m1r - mn1);
            m0r = mn0; m1r = mn1;

            float rs0 = 0.f, rs1 = 0.f;
#pragma unroll
            for (int nt = 0; nt < 8; nt++) {
                sacc[nt][0] = __expf(sacc[nt][0] - mn0);
                sacc[nt][1] = __expf(sacc[nt][1] - mn0);
                sacc[nt][2] = __expf(sacc[nt][2] - mn1);
                sacc[nt][3] = __expf(sacc[nt][3] - mn1);
                rs0 += sacc[nt][0] + sacc[nt][1];
                rs1 += sacc[nt][2] + sacc[nt][3];
            }
            rs0 += __shfl_xor_sync(0xffffffffu, rs0, 1);
            rs0 += __shfl_xor_sync(0xffffffffu, rs0, 2);
            rs1 += __shfl_xor_sync(0xffffffffu, rs1, 1);
            rs1 += __shfl_xor_sync(0xffffffffu, rs1, 2);
            l0r = l0r * al0 + rs0;
            l1r = l1r * al1 + rs1;
#pragma unroll
            for (int nt = 0; nt < 8; nt++) {
                oacc[nt][0] *= al0; oacc[nt][1] *= al0;
                oacc[nt][2] *= al1; oacc[nt][3] *= al1;
            }

            // ---- P fragments (split bf16, A-fragment layout) ----
            uint32_t ph[4][4], pl[4][4];
#pragma unroll
            for (int kc = 0; kc < 4; kc++) {
                split2(sacc[2*kc][0],   sacc[2*kc][1],   ph[kc][0], pl[kc][0]);
                split2(sacc[2*kc][2],   sacc[2*kc][3],   ph[kc][1], pl[kc][1]);
                split2(sacc[2*kc+1][0], sacc[2*kc+1][1], ph[kc][2], pl[kc][2]);
                split2(sacc[2*kc+1][2], sacc[2*kc+1][3], ph[kc][3], pl[kc][3]);
            }

            // ---- O += P V (split) ----
#pragma unroll
            for (int ntp = 0; ntp < 4; ntp++) {
#pragma unroll
                for (int kc = 0; kc < 4; kc++) {
                    const int vrow = kc * 16 + ((g & 1) << 3) + l7;
                    const int vc   = 2 * ntp + (g >> 1);
                    const uint32_t vd = vrow * 128 + ((vc ^ (vrow & 7)) << 4);
                    uint32_t vh[4], vl[4];
                    ldsm4t(vh, sVh + vd);
                    ldsm4t(vl, sVl + vd);
                    mma16816(oacc[2*ntp],   ph[kc], vh);
                    mma16816(oacc[2*ntp+1], ph[kc], vh + 2);
                    mma16816(oacc[2*ntp],   ph[kc], vl);
                    mma16816(oacc[2*ntp+1], ph[kc], vl + 2);
                    mma16816(oacc[2*ntp],   pl[kc], vh);
                    mma16816(oacc[2*ntp+1], pl[kc], vh + 2);
                }
            }
        }
    }

    // ---- epilogue: normalize, split-write y ----
    const float inv0 = 1.f / l0r;
    const float inv1 = 1.f / l1r;
    const size_t tok0 = (size_t)(b * Tq + q0 + wq * 16 + r);
    const size_t tok1 = tok0 + 8;
#pragma unroll
    for (int nt = 0; nt < 8; nt++) {
        const int col = h * Dq + nt * 8 + 2 * t;
        uint32_t h01, l01, h23, l23;
        split2(oacc[nt][0] * inv0, oacc[nt][1] * inv0, h01, l01);
        split2(oacc[nt][2] * inv1, oacc[nt][3] * inv1, h23, l23);
        *(uint32_t*)(yh + tok0 * Cq + col) = h01;
        *(uint32_t*)(yl + tok0 * Cq + col) = l01;
        *(uint32_t*)(yh + tok1 * Cq + col) = h23;
        *(uint32_t*)(yl + tok1 * Cq + col) = l23;
    }
}

// ---------------------------------------------------------------------------
extern "C" void kernel_launch(void* const* d_in, const int* in_sizes, int n_in,
                              void* d_out, int out_size)
{
    const float* x      = (const float*)d_in[0];
    const float* w_attn = (const float*)d_in[1];
    const float* b_attn = (const float*)d_in[2];
    const float* w_proj = (const float*)d_in[3];
    const float* b_proj = (const float*)d_in[4];
    float* out = (float*)d_out;

    __nv_bfloat16 *qkvh, *qkvl, *xh, *xl, *wah, *wal, *yh, *yl, *wph, *wpl;
    cudaGetSymbolAddress((void**)&qkvh, g_qkvh);
    cudaGetSymbolAddress((void**)&qkvl, g_qkvl);
    cudaGetSymbolAddress((void**)&xh,  g_xh);
    cudaGetSymbolAddress((void**)&xl,  g_xl);
    cudaGetSymbolAddress((void**)&wah, g_wah);
    cudaGetSymbolAddress((void**)&wal, g_wal);
    cudaGetSymbolAddress((void**)&yh,  g_yh);
    cudaGetSymbolAddress((void**)&yl,  g_yl);
    cudaGetSymbolAddress((void**)&wph, g_wph);
    cudaGetSymbolAddress((void**)&wpl, g_wpl);

    cudaFuncSetAttribute(gemm_hmma<0>,
                         cudaFuncAttributeMaxDynamicSharedMemorySize, GEMM_SMEM);
    cudaFuncSetAttribute(gemm_hmma<1>,
                         cudaFuncAttributeMaxDynamicSharedMemorySize, GEMM_SMEM);
    cudaFuncSetAttribute(flash_hmma,
                         cudaFuncAttributeMaxDynamicSharedMemorySize, FLASH_SMEM);

    // splits (fp32 -> bf16 hi/lo) for x and weights
    {
        int n1 = NTOK * Cq;
        split_kernel<<<(n1 / 4 + 255) / 256, 256>>>(x, xh, xl, n1);
        int n2 = C3 * Cq;
        split_kernel<<<(n2 / 4 + 255) / 256, 256>>>(w_attn, wah, wal, n2);
        int n3 = Cq * Cq;
        split_kernel<<<(n3 / 4 + 255) / 256, 256>>>(w_proj, wph, wpl, n3);
    }

    // 1) qkv = x @ w_attn^T + b_attn  -> split bf16 directly
    {
        dim3 grid(C3 / BN, NTOK / BM);
        gemm_hmma<1><<<grid, 256, GEMM_SMEM>>>(xh, xl, wah, wal, b_attn,
                                               nullptr, qkvh, qkvl,
                                               NTOK, C3, Cq);
    }
    // 2) tensorized flash attention -> split y
    {
        dim3 grid(Tq / 128, Bq * Hq);
        flash_hmma<<<grid, 256, FLASH_SMEM>>>(qkvh, qkvl, yh, yl);
    }
    // 3) out = y @ w_proj^T + b_proj  (fp32 out)
    {
        dim3 grid(Cq / BN, NTOK / BM);
        gemm_hmma<0><<<grid, 256, GEMM_SMEM>>>(yh, yl, wph, wpl, b_proj,
                                               out, nullptr, nullptr,
                                               NTOK, Cq, Cq);
    }
}